// round 2
// baseline (speedup 1.0000x reference)
#include <cuda_runtime.h>
#include <cstring>

// Problem constants (fixed by reference_code)
#define Bc 2
#define Nc 65536
#define Hc 128
#define Wc 128
#define HWc 16384
#define Gsplit 32              // split-K factor over gaussians
#define KN (Nc / Gsplit)       // 2048 gaussians per block
#define KC 32                  // chunk of gaussians staged in smem
#define NTILES 8               // 2 x-tiles (64 wide) * 4 y-tiles (32 tall)
#define TDIMX 64
#define TDIMY 32

typedef unsigned long long ull;

// Scratch (static __device__ arrays — no allocation at runtime)
__device__ float4 g_params[Bc * Nc];                  // proj_x, proj_y, a=-0.5/var, opacity
__device__ float  g_part[Bc * Gsplit * 4 * HWc];      // split-K partials (r,g,b,den)

// ---- packed fp32x2 helpers (FFMA2 — ptxas never emits these on its own) ----
__device__ __forceinline__ void ffma2(ull& d, ull a, ull b) {
    asm("fma.rn.f32x2 %0, %1, %2, %0;" : "+l"(d) : "l"(a), "l"(b));
}
__device__ __forceinline__ ull fmul2(ull a, ull b) {
    ull r; asm("mul.rn.f32x2 %0, %1, %2;" : "=l"(r) : "l"(a), "l"(b)); return r;
}
__device__ __forceinline__ float2 unpack2(ull v) {
    float2 f; asm("mov.b64 {%0, %1}, %2;" : "=f"(f.x), "=f"(f.y) : "l"(v)); return f;
}

// ---------------------------------------------------------------------------
// Kernel 1: per-(camera, gaussian) projection parameters
// ---------------------------------------------------------------------------
__global__ void k_params(const float* __restrict__ pos,
                         const float* __restrict__ opa,
                         const float* __restrict__ scl,
                         const float* __restrict__ qv,
                         const float* __restrict__ tv,
                         const float* __restrict__ fx_,
                         const float* __restrict__ fy_,
                         const float* __restrict__ cx_,
                         const float* __restrict__ cy_) {
    int idx = blockIdx.x * blockDim.x + threadIdx.x;
    if (idx >= Bc * Nc) return;
    int b = idx >> 16;            // Nc = 65536
    int n = idx & (Nc - 1);

    float qw = qv[b * 4 + 0], qx = qv[b * 4 + 1], qy = qv[b * 4 + 2], qz = qv[b * 4 + 3];
    float inv = rsqrtf(qw * qw + qx * qx + qy * qy + qz * qz);
    qw *= inv; qx *= inv; qy *= inv; qz *= inv;

    float R00 = 1.f - 2.f * (qy * qy + qz * qz);
    float R01 = 2.f * (qx * qy - qz * qw);
    float R02 = 2.f * (qx * qz + qy * qw);
    float R10 = 2.f * (qx * qy + qz * qw);
    float R11 = 1.f - 2.f * (qx * qx + qz * qz);
    float R12 = 2.f * (qy * qz - qx * qw);
    float R20 = 2.f * (qx * qz - qy * qw);
    float R21 = 2.f * (qy * qz + qx * qw);
    float R22 = 1.f - 2.f * (qx * qx + qy * qy);

    float px = pos[3 * n], py = pos[3 * n + 1], pz = pos[3 * n + 2];
    float cxm = R00 * px + R01 * py + R02 * pz + tv[b * 3 + 0];
    float cym = R10 * px + R11 * py + R12 * pz + tv[b * 3 + 1];
    float czm = R20 * px + R21 * py + R22 * pz + tv[b * 3 + 2];

    float projx = cxm / czm * fx_[0] + cx_[0];
    float projy = cym / czm * fy_[0] + cy_[0];
    float s = scl[n];
    float a = -0.5f / (s * s);

    g_params[idx] = make_float4(projx, projy, a, opa[n]);
}

// ---------------------------------------------------------------------------
// Kernel 2: fused separable splat / rank-1 GEMM with split-K (packed fp32x2)
//   block = 256 threads, tile = 64x * 32y pixels, 2048 gaussians
//   per chunk of 32 gaussians: stage u[k][64], (v,v)[k][32], (c,c)[k] in smem
// ---------------------------------------------------------------------------
__global__ void __launch_bounds__(256) k_splat(const float* __restrict__ colors) {
    __shared__ float      us[KC][TDIMX];    // u[k][x]                      (8 KB)
    __shared__ float2     vs2[KC][TDIMY];   // (v,v) broadcast pairs, op folded (8 KB)
    __shared__ ulonglong2 cs2[KC][2];       // [(cr,cr),(cg,cg)] [(cb,cb),(1,1)] (1 KB)

    const int t    = threadIdx.x;
    const int g    = blockIdx.x;          // k-split index
    const int tile = blockIdx.y;          // 0..7
    const int b    = blockIdx.z;          // camera
    const int x0   = (tile & 1) * TDIMX;
    const int y0   = (tile >> 1) * TDIMY;
    const int kbase0 = g * KN;

    // thread -> 4x * 2y pixel micro-tile
    const int tx  = t & 15;               // px base = x0 + 4*tx
    const int tyy = t >> 4;               // py base = y0 + 2*tyy
    const int xu  = t & 63, ku0 = t >> 6; // u-stage mapping
    const int yv  = t & 31, kv0 = t >> 5; // v-stage mapping

    // acc[y][xpair][ch] as packed f32x2 (two x pixels per reg pair)
    ull acc[2][2][4];
#pragma unroll
    for (int yi = 0; yi < 2; yi++)
#pragma unroll
        for (int xp = 0; xp < 2; xp++)
#pragma unroll
            for (int ch = 0; ch < 4; ch++) acc[yi][xp][ch] = 0ULL;

    const float4* __restrict__ prm = &g_params[b * Nc];

    for (int kb = 0; kb < KN; kb += KC) {
        const int kbase = kbase0 + kb;
        __syncthreads();   // previous chunk consumers done

        // ---- stage u: 32k x 64x, conflict-free STS (consecutive x per warp)
#pragma unroll
        for (int i = 0; i < 8; i++) {
            int k = ku0 + i * 4;
            float4 pr = prm[kbase + k];
            float dx = (float)(x0 + xu) - pr.x;
            us[k][xu] = __expf(pr.z * dx * dx);
        }
        // ---- stage v as broadcast pairs (opacity folded in)
#pragma unroll
        for (int i = 0; i < 4; i++) {
            int k = kv0 + i * 8;
            float4 pr = prm[kbase + k];
            float dy = (float)(y0 + yv) - pr.y;
            float v = pr.w * __expf(pr.z * dy * dy);
            vs2[k][yv] = make_float2(v, v);
        }
        // ---- stage colors as broadcast pairs
        if (t < 2 * KC) {
            int k = t >> 1, half = t & 1;
            int n = kbase + k;
            float a0 = colors[3 * n + 2 * half];             // cr or cb
            float a1 = (half == 0) ? colors[3 * n + 1] : 1.f; // cg or 1 (den)
            ulonglong2 packed;
            float2 p0 = make_float2(a0, a0), p1 = make_float2(a1, a1);
            memcpy(&packed.x, &p0, 8);
            memcpy(&packed.y, &p1, 8);
            cs2[k][half] = packed;
        }
        __syncthreads();

        // ---- inner rank-1 accumulation: 20 packed FMA-pipe ops + 4 LDS.128 per k
#pragma unroll 8
        for (int k = 0; k < KC; k++) {
            ulonglong2 u  = *reinterpret_cast<const ulonglong2*>(&us[k][tx * 4]);  // (u0,u1),(u2,u3)
            ulonglong2 vv = *reinterpret_cast<const ulonglong2*>(&vs2[k][tyy * 2]); // (v0,v0),(v1,v1)
            ulonglong2 cA = cs2[k][0];  // (cr,cr),(cg,cg)   broadcast
            ulonglong2 cB = cs2[k][1];  // (cb,cb),(1,1)     broadcast

            ull w00 = fmul2(vv.x, u.x);   // y0, x01
            ull w01 = fmul2(vv.x, u.y);   // y0, x23
            ull w10 = fmul2(vv.y, u.x);   // y1, x01
            ull w11 = fmul2(vv.y, u.y);   // y1, x23

            ffma2(acc[0][0][0], w00, cA.x); ffma2(acc[0][0][1], w00, cA.y);
            ffma2(acc[0][0][2], w00, cB.x); ffma2(acc[0][0][3], w00, cB.y);
            ffma2(acc[0][1][0], w01, cA.x); ffma2(acc[0][1][1], w01, cA.y);
            ffma2(acc[0][1][2], w01, cB.x); ffma2(acc[0][1][3], w01, cB.y);
            ffma2(acc[1][0][0], w10, cA.x); ffma2(acc[1][0][1], w10, cA.y);
            ffma2(acc[1][0][2], w10, cB.x); ffma2(acc[1][0][3], w10, cB.y);
            ffma2(acc[1][1][0], w11, cA.x); ffma2(acc[1][1][1], w11, cA.y);
            ffma2(acc[1][1][2], w11, cB.x); ffma2(acc[1][1][3], w11, cB.y);
        }
    }

    // ---- write deterministic split-K partials
    const int base_bg = ((b * Gsplit + g) * 4) * HWc;
#pragma unroll
    for (int yi = 0; yi < 2; yi++) {
        int pyy = y0 + tyy * 2 + yi;
#pragma unroll
        for (int xp = 0; xp < 2; xp++) {
#pragma unroll
            for (int ch = 0; ch < 4; ch++) {
                float2 f = unpack2(acc[yi][xp][ch]);
                int pxx  = x0 + tx * 4 + xp * 2;
                int pidx = pyy * Wc + pxx;
                g_part[base_bg + ch * HWc + pidx]     = f.x;
                g_part[base_bg + ch * HWc + pidx + 1] = f.y;
            }
        }
    }
}

// ---------------------------------------------------------------------------
// Kernel 3: reduce split-K partials, add 32*EPS (one EPS per reference chunk),
//           divide, write (B,3,H,W)
// ---------------------------------------------------------------------------
__global__ void k_finalize(float* __restrict__ out) {
    int idx = blockIdx.x * blockDim.x + threadIdx.x;
    if (idx >= Bc * HWc) return;
    int b = idx >> 14;           // HWc = 16384
    int p = idx & (HWc - 1);

    float r = 0.f, gg = 0.f, bb = 0.f;
    float d = 32.0f * 1e-8f;     // n_chunks(=32) * EPS added by reference scan
#pragma unroll
    for (int s = 0; s < Gsplit; s++) {
        int base = ((b * Gsplit + s) * 4) * HWc + p;
        r  += g_part[base];
        gg += g_part[base + HWc];
        bb += g_part[base + 2 * HWc];
        d  += g_part[base + 3 * HWc];
    }
    float inv = 1.0f / fmaxf(d, 1e-8f);
    out[(b * 3 + 0) * HWc + p] = r  * inv;
    out[(b * 3 + 1) * HWc + p] = gg * inv;
    out[(b * 3 + 2) * HWc + p] = bb * inv;
}

// ---------------------------------------------------------------------------
extern "C" void kernel_launch(void* const* d_in, const int* in_sizes, int n_in,
                              void* d_out, int out_size) {
    const float* pos = (const float*)d_in[0];
    const float* col = (const float*)d_in[1];
    const float* opa = (const float*)d_in[2];
    const float* scl = (const float*)d_in[3];
    const float* qv  = (const float*)d_in[4];
    const float* tv  = (const float*)d_in[5];
    const float* fx  = (const float*)d_in[6];
    const float* fy  = (const float*)d_in[7];
    const float* cx  = (const float*)d_in[8];
    const float* cy  = (const float*)d_in[9];

    k_params<<<(Bc * Nc) / 256, 256>>>(pos, opa, scl, qv, tv, fx, fy, cx, cy);

    dim3 grid(Gsplit, NTILES, Bc);   // 32 * 8 * 2 = 512 blocks
    k_splat<<<grid, 256>>>(col);

    k_finalize<<<(Bc * HWc) / 256, 256>>>((float*)d_out);
}

// round 3
// speedup vs baseline: 1.1849x; 1.1849x over previous
#include <cuda_runtime.h>

// Problem constants (fixed by reference_code)
#define Bc 2
#define Nc 65536
#define Hc 128
#define Wc 128
#define HWc 16384
#define Gsplit 32              // split-K factor over gaussians
#define KN (Nc / Gsplit)       // 2048 gaussians per block
#define KC 32                  // chunk of gaussians staged in smem
#define NTILES 8               // 2 x-tiles (64 wide) * 4 y-tiles (32 tall)
#define TDIMX 64
#define TDIMY 32

// Scratch (static __device__ arrays — no allocation at runtime)
__device__ float4 g_params[Bc * Nc];                  // proj_x, proj_y, a=-0.5/var, opacity
__device__ float  g_part[Bc * Gsplit * 4 * HWc];      // split-K partials (r,g,b,den)

// ---------------------------------------------------------------------------
// Kernel 1: per-(camera, gaussian) projection parameters
// ---------------------------------------------------------------------------
__global__ void k_params(const float* __restrict__ pos,
                         const float* __restrict__ opa,
                         const float* __restrict__ scl,
                         const float* __restrict__ qv,
                         const float* __restrict__ tv,
                         const float* __restrict__ fx_,
                         const float* __restrict__ fy_,
                         const float* __restrict__ cx_,
                         const float* __restrict__ cy_) {
    int idx = blockIdx.x * blockDim.x + threadIdx.x;
    if (idx >= Bc * Nc) return;
    int b = idx >> 16;            // Nc = 65536
    int n = idx & (Nc - 1);

    float qw = qv[b * 4 + 0], qx = qv[b * 4 + 1], qy = qv[b * 4 + 2], qz = qv[b * 4 + 3];
    float inv = rsqrtf(qw * qw + qx * qx + qy * qy + qz * qz);
    qw *= inv; qx *= inv; qy *= inv; qz *= inv;

    float R00 = 1.f - 2.f * (qy * qy + qz * qz);
    float R01 = 2.f * (qx * qy - qz * qw);
    float R02 = 2.f * (qx * qz + qy * qw);
    float R10 = 2.f * (qx * qy + qz * qw);
    float R11 = 1.f - 2.f * (qx * qx + qz * qz);
    float R12 = 2.f * (qy * qz - qx * qw);
    float R20 = 2.f * (qx * qz - qy * qw);
    float R21 = 2.f * (qy * qz + qx * qw);
    float R22 = 1.f - 2.f * (qx * qx + qy * qy);

    float px = pos[3 * n], py = pos[3 * n + 1], pz = pos[3 * n + 2];
    // p_cam = positions @ R.T + t
    float cxm = R00 * px + R01 * py + R02 * pz + tv[b * 3 + 0];
    float cym = R10 * px + R11 * py + R12 * pz + tv[b * 3 + 1];
    float czm = R20 * px + R21 * py + R22 * pz + tv[b * 3 + 2];

    float projx = cxm / czm * fx_[0] + cx_[0];
    float projy = cym / czm * fy_[0] + cy_[0];
    float s = scl[n];
    float a = -0.5f / (s * s);

    g_params[idx] = make_float4(projx, projy, a, opa[n]);
}

// ---------------------------------------------------------------------------
// Kernel 2: fused separable splat with pre-folded per-row channel weights.
//   block = 256 threads, tile = 64x * 32y pixels, 2048 gaussians, split-K.
//   Staging per 32-gaussian chunk:
//     us[k][x]  = exp(a*dx^2)                          (8 KB)
//     ds[k][y]  = (v*cr, v*cg, v*cb, v), v=opa*exp(a*dy^2)  (16 KB)
//   Inner loop per gaussian per thread: 3x LDS.128 + 32 FFMA, ZERO muls.
// ---------------------------------------------------------------------------
__global__ void __launch_bounds__(256) k_splat(const float* __restrict__ colors) {
    __shared__ float  us[KC][TDIMX];     // 8 KB
    __shared__ float4 ds[KC][TDIMY];     // 16 KB

    const int t    = threadIdx.x;
    const int g    = blockIdx.x;          // k-split index
    const int tile = blockIdx.y;          // 0..7
    const int b    = blockIdx.z;          // camera
    const int x0   = (tile & 1) * TDIMX;
    const int y0   = (tile >> 1) * TDIMY;
    const int kbase0 = g * KN;

    // thread -> 4x * 2y pixel micro-tile
    const int tx  = t & 15;               // px base = x0 + 4*tx
    const int tyy = t >> 4;               // py base = y0 + 2*tyy
    const int xu  = t & 63, ku0 = t >> 6; // u-stage mapping (warp-uniform k)
    const int yv  = t & 31, kd0 = t >> 5; // d-stage mapping (warp-uniform k)

    float acc[2][4][4];
#pragma unroll
    for (int yi = 0; yi < 2; yi++)
#pragma unroll
        for (int xi = 0; xi < 4; xi++)
#pragma unroll
            for (int ch = 0; ch < 4; ch++) acc[yi][xi][ch] = 0.f;

    const float4* __restrict__ prm = &g_params[b * Nc];

    for (int kb = 0; kb < KN; kb += KC) {
        const int kbase = kbase0 + kb;
        __syncthreads();   // previous chunk consumers done

        // ---- stage u: 32k x 64x, conflict-free STS (consecutive x per warp)
#pragma unroll
        for (int i = 0; i < 8; i++) {
            int k = ku0 + i * 4;
            float4 pr = prm[kbase + k];
            float dx = (float)(x0 + xu) - pr.x;
            us[k][xu] = __expf(pr.z * dx * dx);
        }
        // ---- stage d: per (k,y) fold opacity*expy into all 4 channels
#pragma unroll
        for (int i = 0; i < 4; i++) {
            int k = kd0 + i * 8;
            int n = kbase + k;
            float4 pr = prm[n];
            float dy = (float)(y0 + yv) - pr.y;
            float v  = pr.w * __expf(pr.z * dy * dy);
            float cr = __ldg(&colors[3 * n]);
            float cg = __ldg(&colors[3 * n + 1]);
            float cb = __ldg(&colors[3 * n + 2]);
            ds[k][yv] = make_float4(v * cr, v * cg, v * cb, v);
        }
        __syncthreads();

        // ---- inner accumulation: 32 FFMA + 3 LDS.128 per k per thread
#pragma unroll 8
        for (int k = 0; k < KC; k++) {
            float4 u4 = *reinterpret_cast<const float4*>(&us[k][tx * 4]);
            float4 d0 = ds[k][tyy * 2];
            float4 d1 = ds[k][tyy * 2 + 1];
            float uu[4] = {u4.x, u4.y, u4.z, u4.w};
#pragma unroll
            for (int xi = 0; xi < 4; xi++) {
                acc[0][xi][0] += uu[xi] * d0.x;
                acc[0][xi][1] += uu[xi] * d0.y;
                acc[0][xi][2] += uu[xi] * d0.z;
                acc[0][xi][3] += uu[xi] * d0.w;
                acc[1][xi][0] += uu[xi] * d1.x;
                acc[1][xi][1] += uu[xi] * d1.y;
                acc[1][xi][2] += uu[xi] * d1.z;
                acc[1][xi][3] += uu[xi] * d1.w;
            }
        }
    }

    // ---- write deterministic split-K partials
    const int base_bg = ((b * Gsplit + g) * 4) * HWc;
#pragma unroll
    for (int yi = 0; yi < 2; yi++) {
        int pyy = y0 + tyy * 2 + yi;
#pragma unroll
        for (int xi = 0; xi < 4; xi++) {
            int pxx  = x0 + tx * 4 + xi;
            int pidx = pyy * Wc + pxx;
#pragma unroll
            for (int ch = 0; ch < 4; ch++)
                g_part[base_bg + ch * HWc + pidx] = acc[yi][xi][ch];
        }
    }
}

// ---------------------------------------------------------------------------
// Kernel 3: reduce split-K partials, add 32*EPS (one EPS per reference chunk),
//           divide, write (B,3,H,W)
// ---------------------------------------------------------------------------
__global__ void k_finalize(float* __restrict__ out) {
    int idx = blockIdx.x * blockDim.x + threadIdx.x;
    if (idx >= Bc * HWc) return;
    int b = idx >> 14;           // HWc = 16384
    int p = idx & (HWc - 1);

    float r = 0.f, gg = 0.f, bb = 0.f;
    float d = 32.0f * 1e-8f;     // n_chunks(=32) * EPS added by reference scan
#pragma unroll
    for (int s = 0; s < Gsplit; s++) {
        int base = ((b * Gsplit + s) * 4) * HWc + p;
        r  += g_part[base];
        gg += g_part[base + HWc];
        bb += g_part[base + 2 * HWc];
        d  += g_part[base + 3 * HWc];
    }
    float inv = 1.0f / fmaxf(d, 1e-8f);
    out[(b * 3 + 0) * HWc + p] = r  * inv;
    out[(b * 3 + 1) * HWc + p] = gg * inv;
    out[(b * 3 + 2) * HWc + p] = bb * inv;
}

// ---------------------------------------------------------------------------
extern "C" void kernel_launch(void* const* d_in, const int* in_sizes, int n_in,
                              void* d_out, int out_size) {
    const float* pos = (const float*)d_in[0];
    const float* col = (const float*)d_in[1];
    const float* opa = (const float*)d_in[2];
    const float* scl = (const float*)d_in[3];
    const float* qv  = (const float*)d_in[4];
    const float* tv  = (const float*)d_in[5];
    const float* fx  = (const float*)d_in[6];
    const float* fy  = (const float*)d_in[7];
    const float* cx  = (const float*)d_in[8];
    const float* cy  = (const float*)d_in[9];

    k_params<<<(Bc * Nc) / 256, 256>>>(pos, opa, scl, qv, tv, fx, fy, cx, cy);

    dim3 grid(Gsplit, NTILES, Bc);   // 32 * 8 * 2 = 512 blocks
    k_splat<<<grid, 256>>>(col);

    k_finalize<<<(Bc * HWc) / 256, 256>>>((float*)d_out);
}

// round 4
// speedup vs baseline: 3.2266x; 2.7230x over previous
#include <cuda_runtime.h>

// Problem constants (fixed by reference_code)
#define Bc 2
#define Nc 65536
#define Hc 128
#define Wc 128
#define HWc 16384
#define Gsplit 64              // split-K factor over gaussians
#define KN (Nc / Gsplit)       // 1024 gaussians per block range
#define KC 32                  // chunk of gaussians staged in smem
#define NTILES 8               // 2 x-tiles (64 wide) * 4 y-tiles (32 tall)
#define TDIMX 64
#define TDIMY 32
// cutoff: op*exp(a*d^2) <= e^-20.8 ~ 1e-9  -> include iff a*dist2 >= -20.8
#define CULL_LN (-20.8f)

// Scratch (static __device__ arrays — no allocation at runtime)
__device__ float4 g_params[Bc * Nc];                  // proj_x, proj_y, a=-0.5/var, opacity
__device__ float  g_part[Bc * Gsplit * 4 * HWc];      // split-K partials (r,g,b,den)

// ---------------------------------------------------------------------------
// Kernel 1: per-(camera, gaussian) projection parameters
// ---------------------------------------------------------------------------
__global__ void k_params(const float* __restrict__ pos,
                         const float* __restrict__ opa,
                         const float* __restrict__ scl,
                         const float* __restrict__ qv,
                         const float* __restrict__ tv,
                         const float* __restrict__ fx_,
                         const float* __restrict__ fy_,
                         const float* __restrict__ cx_,
                         const float* __restrict__ cy_) {
    int idx = blockIdx.x * blockDim.x + threadIdx.x;
    if (idx >= Bc * Nc) return;
    int b = idx >> 16;            // Nc = 65536
    int n = idx & (Nc - 1);

    float qw = qv[b * 4 + 0], qx = qv[b * 4 + 1], qy = qv[b * 4 + 2], qz = qv[b * 4 + 3];
    float inv = rsqrtf(qw * qw + qx * qx + qy * qy + qz * qz);
    qw *= inv; qx *= inv; qy *= inv; qz *= inv;

    float R00 = 1.f - 2.f * (qy * qy + qz * qz);
    float R01 = 2.f * (qx * qy - qz * qw);
    float R02 = 2.f * (qx * qz + qy * qw);
    float R10 = 2.f * (qx * qy + qz * qw);
    float R11 = 1.f - 2.f * (qx * qx + qz * qz);
    float R12 = 2.f * (qy * qz - qx * qw);
    float R20 = 2.f * (qx * qz - qy * qw);
    float R21 = 2.f * (qy * qz + qx * qw);
    float R22 = 1.f - 2.f * (qx * qx + qy * qy);

    float px = pos[3 * n], py = pos[3 * n + 1], pz = pos[3 * n + 2];
    // p_cam = positions @ R.T + t
    float cxm = R00 * px + R01 * py + R02 * pz + tv[b * 3 + 0];
    float cym = R10 * px + R11 * py + R12 * pz + tv[b * 3 + 1];
    float czm = R20 * px + R21 * py + R22 * pz + tv[b * 3 + 2];

    float projx = cxm / czm * fx_[0] + cx_[0];
    float projy = cym / czm * fy_[0] + cy_[0];
    float s = scl[n];
    float a = -0.5f / (s * s);

    g_params[idx] = make_float4(projx, projy, a, opa[n]);
}

// ---------------------------------------------------------------------------
// Kernel 2: culled separable splat.
//   block = (g in 64 splits, tile in 8, camera in 2) -> 1024 blocks, 256 thr.
//   Phase A: deterministic ballot/prefix compaction of the block's 1024
//            gaussians against the tile (a*dist^2 >= -20.8 cutoff).
//   Phase B: chunked rank-1 accumulation over the compacted list:
//            us[k][x]=exp(a dx^2); ds[k][y]=(v cr, v cg, v cb, v).
//            Inner loop: 3x LDS.128 + 32 FFMA per gaussian per thread.
// ---------------------------------------------------------------------------
__global__ void __launch_bounds__(256) k_splat(const float* __restrict__ colors) {
    __shared__ float  us[KC][TDIMX];        // 8 KB
    __shared__ float4 ds[KC][TDIMY];        // 16 KB
    __shared__ unsigned short list[KN];     // 2 KB
    __shared__ int warp_cnt[8];

    const int t    = threadIdx.x;
    const int g    = blockIdx.x;          // k-split index
    const int tile = blockIdx.y;          // 0..7
    const int b    = blockIdx.z;          // camera
    const int x0   = (tile & 1) * TDIMX;
    const int y0   = (tile >> 1) * TDIMY;
    const int kbase0 = g * KN;
    const int wid  = t >> 5, lane = t & 31;

    const float4* __restrict__ prm = &g_params[b * Nc];

    // ---------------- Phase A: compaction (index-ordered, deterministic) ----
    int running = 0;
    const float xlo = (float)x0, xhi = (float)(x0 + TDIMX - 1);
    const float ylo = (float)y0, yhi = (float)(y0 + TDIMY - 1);
#pragma unroll
    for (int p = 0; p < KN / 256; p++) {
        int k = p * 256 + t;              // warp w covers consecutive 32 -> order kept
        float4 pr = prm[kbase0 + k];
        float ex = fmaxf(fmaxf(xlo - pr.x, pr.x - xhi), 0.0f);
        float ey = fmaxf(fmaxf(ylo - pr.y, pr.y - yhi), 0.0f);
        bool inc = pr.z * (ex * ex + ey * ey) >= CULL_LN;
        unsigned m = __ballot_sync(0xffffffffu, inc);
        if (lane == 0) warp_cnt[wid] = __popc(m);
        __syncthreads();
        int base = running, tot = 0;
#pragma unroll
        for (int w = 0; w < 8; w++) {
            int c = warp_cnt[w];
            if (w < wid) base += c;
            tot += c;
        }
        if (inc) list[base + __popc(m & ((1u << lane) - 1u))] = (unsigned short)k;
        running += tot;
        __syncthreads();
    }
    const int cnt = running;

    // ---------------- Phase B: chunked accumulation over the list ----------
    // thread -> 4x * 2y pixel micro-tile
    const int tx  = t & 15;               // px base = x0 + 4*tx
    const int tyy = t >> 4;               // py base = y0 + 2*tyy
    const int xu  = t & 63, ku0 = t >> 6; // u-stage: warp-uniform k
    const int yv  = t & 31, kd0 = t >> 5; // d-stage: warp-uniform k

    float acc[2][4][4];
#pragma unroll
    for (int yi = 0; yi < 2; yi++)
#pragma unroll
        for (int xi = 0; xi < 4; xi++)
#pragma unroll
            for (int ch = 0; ch < 4; ch++) acc[yi][xi][ch] = 0.f;

    for (int kb = 0; kb < cnt; kb += KC) {
        __syncthreads();   // previous chunk consumers done

        // ---- stage u: per warp a single k (broadcast param load)
#pragma unroll
        for (int i = 0; i < 8; i++) {
            int k = ku0 + i * 4;
            int kk = kb + k;
            float u = 0.f;
            if (kk < cnt) {
                int idx = (int)list[kk];
                float4 pr = prm[kbase0 + idx];
                float dx = (float)(x0 + xu) - pr.x;
                u = __expf(pr.z * dx * dx);
            }
            us[k][xu] = u;
        }
        // ---- stage d: fold opacity*expy and colors per (k,y)
#pragma unroll
        for (int i = 0; i < 4; i++) {
            int k = kd0 + i * 8;
            int kk = kb + k;
            float4 dval = make_float4(0.f, 0.f, 0.f, 0.f);
            if (kk < cnt) {
                int idx = (int)list[kk];
                int n = kbase0 + idx;
                float4 pr = prm[n];
                float dy = (float)(y0 + yv) - pr.y;
                float v  = pr.w * __expf(pr.z * dy * dy);
                float cr = __ldg(&colors[3 * n]);
                float cg = __ldg(&colors[3 * n + 1]);
                float cb = __ldg(&colors[3 * n + 2]);
                dval = make_float4(v * cr, v * cg, v * cb, v);
            }
            ds[k][yv] = dval;
        }
        __syncthreads();

        // ---- inner accumulation: 32 FFMA + 3 LDS.128 per k per thread
#pragma unroll 8
        for (int k = 0; k < KC; k++) {
            float4 u4 = *reinterpret_cast<const float4*>(&us[k][tx * 4]);
            float4 d0 = ds[k][tyy * 2];
            float4 d1 = ds[k][tyy * 2 + 1];
            float uu[4] = {u4.x, u4.y, u4.z, u4.w};
#pragma unroll
            for (int xi = 0; xi < 4; xi++) {
                acc[0][xi][0] += uu[xi] * d0.x;
                acc[0][xi][1] += uu[xi] * d0.y;
                acc[0][xi][2] += uu[xi] * d0.z;
                acc[0][xi][3] += uu[xi] * d0.w;
                acc[1][xi][0] += uu[xi] * d1.x;
                acc[1][xi][1] += uu[xi] * d1.y;
                acc[1][xi][2] += uu[xi] * d1.z;
                acc[1][xi][3] += uu[xi] * d1.w;
            }
        }
    }

    // ---- write deterministic split-K partials
    const int base_bg = ((b * Gsplit + g) * 4) * HWc;
#pragma unroll
    for (int yi = 0; yi < 2; yi++) {
        int pyy = y0 + tyy * 2 + yi;
#pragma unroll
        for (int xi = 0; xi < 4; xi++) {
            int pxx  = x0 + tx * 4 + xi;
            int pidx = pyy * Wc + pxx;
#pragma unroll
            for (int ch = 0; ch < 4; ch++)
                g_part[base_bg + ch * HWc + pidx] = acc[yi][xi][ch];
        }
    }
}

// ---------------------------------------------------------------------------
// Kernel 3: reduce split-K partials, add 32*EPS (one EPS per reference chunk),
//           divide, write (B,3,H,W)
// ---------------------------------------------------------------------------
__global__ void k_finalize(float* __restrict__ out) {
    int idx = blockIdx.x * blockDim.x + threadIdx.x;
    if (idx >= Bc * HWc) return;
    int b = idx >> 14;           // HWc = 16384
    int p = idx & (HWc - 1);

    float r = 0.f, gg = 0.f, bb = 0.f;
    float d = 32.0f * 1e-8f;     // n_chunks(=32 of 2048) * EPS in reference scan
#pragma unroll
    for (int s = 0; s < Gsplit; s++) {
        int base = ((b * Gsplit + s) * 4) * HWc + p;
        r  += g_part[base];
        gg += g_part[base + HWc];
        bb += g_part[base + 2 * HWc];
        d  += g_part[base + 3 * HWc];
    }
    float inv = 1.0f / fmaxf(d, 1e-8f);
    out[(b * 3 + 0) * HWc + p] = r  * inv;
    out[(b * 3 + 1) * HWc + p] = gg * inv;
    out[(b * 3 + 2) * HWc + p] = bb * inv;
}

// ---------------------------------------------------------------------------
extern "C" void kernel_launch(void* const* d_in, const int* in_sizes, int n_in,
                              void* d_out, int out_size) {
    const float* pos = (const float*)d_in[0];
    const float* col = (const float*)d_in[1];
    const float* opa = (const float*)d_in[2];
    const float* scl = (const float*)d_in[3];
    const float* qv  = (const float*)d_in[4];
    const float* tv  = (const float*)d_in[5];
    const float* fx  = (const float*)d_in[6];
    const float* fy  = (const float*)d_in[7];
    const float* cx  = (const float*)d_in[8];
    const float* cy  = (const float*)d_in[9];

    k_params<<<(Bc * Nc) / 256, 256>>>(pos, opa, scl, qv, tv, fx, fy, cx, cy);

    dim3 grid(Gsplit, NTILES, Bc);   // 64 * 8 * 2 = 1024 blocks
    k_splat<<<grid, 256>>>(col);

    k_finalize<<<(Bc * HWc) / 256, 256>>>((float*)d_out);
}